// round 1
// baseline (speedup 1.0000x reference)
#include <cuda_runtime.h>

// Problem constants (fixed shapes from reference)
#define D      512
#define N_ROWS 16384
#define K_CB   8192

#define BM 128   // rows per block
#define BN 128   // codebook entries per tile
#define BK 16    // depth chunk
#define TM 8
#define TN 8
// 16x16 = 256 threads

__device__ float g_e2[K_CB];

// ---------------------------------------------------------------------------
// Kernel 1: codebook squared norms. One block per codebook row.
// 128 threads * 1 float4 each = 512 floats.
// ---------------------------------------------------------------------------
__global__ void __launch_bounds__(128) e2_kernel(const float* __restrict__ cb) {
    int row = blockIdx.x;
    float4 v = reinterpret_cast<const float4*>(cb + (size_t)row * D)[threadIdx.x];
    float s = v.x * v.x + v.y * v.y + v.z * v.z + v.w * v.w;
    #pragma unroll
    for (int o = 16; o; o >>= 1) s += __shfl_xor_sync(0xffffffffu, s, o);
    __shared__ float ws[4];
    if ((threadIdx.x & 31) == 0) ws[threadIdx.x >> 5] = s;
    __syncthreads();
    if (threadIdx.x == 0) g_e2[row] = ws[0] + ws[1] + ws[2] + ws[3];
}

// ---------------------------------------------------------------------------
// Kernel 2: fused distance GEMM + argmin + gather.
// Each block owns BM=128 rows of x, scans all 8192 codebook entries in
// BN=128 tiles, tracking per-row running (min dist, index), then gathers
// codebook[best] into out.
// dist = e2[c] - 2 * dot(x_r, e_c)   (x^2 term is row-constant, dropped)
// ---------------------------------------------------------------------------
__global__ void __launch_bounds__(256) vq_kernel(const float* __restrict__ x,
                                                 const float* __restrict__ cb,
                                                 float* __restrict__ out) {
    __shared__ float As[BK][BM];      // x^T chunk   (k-major for FMA loop)
    __shared__ float Bs[BK][BN];      // cb^T chunk
    __shared__ float e2s[BN];
    __shared__ float bestv[BM];
    __shared__ int   besti[BM];

    const int tid = threadIdx.x;
    const int tx = tid & 15;          // codebook-tile direction
    const int ty = tid >> 4;          // row direction
    const int rowBase = blockIdx.x * BM;

    for (int i = tid; i < BM; i += 256) { bestv[i] = 3.4028235e38f; besti[i] = 0; }

    for (int cb0 = 0; cb0 < K_CB; cb0 += BN) {
        __syncthreads();                       // prev epilogue done with e2s
        if (tid < BN) e2s[tid] = g_e2[cb0 + tid];

        float acc[TM][TN];
        #pragma unroll
        for (int i = 0; i < TM; i++)
            #pragma unroll
            for (int j = 0; j < TN; j++) acc[i][j] = 0.0f;

        for (int d0 = 0; d0 < D; d0 += BK) {
            __syncthreads();                   // readers of prev As/Bs done
            // Load 128x16 of x and cb, transposed into smem.
            // 512 float4 per matrix, 2 per thread.
            #pragma unroll
            for (int it = 0; it < 2; it++) {
                int idx = tid + it * 256;      // 0..511
                int m  = idx >> 2;             // row within tile (0..127)
                int kq = idx & 3;              // which float4 along depth
                float4 va = *reinterpret_cast<const float4*>(
                    x + (size_t)(rowBase + m) * D + d0 + kq * 4);
                As[kq * 4 + 0][m] = va.x;
                As[kq * 4 + 1][m] = va.y;
                As[kq * 4 + 2][m] = va.z;
                As[kq * 4 + 3][m] = va.w;
                float4 vb = *reinterpret_cast<const float4*>(
                    cb + (size_t)(cb0 + m) * D + d0 + kq * 4);
                Bs[kq * 4 + 0][m] = vb.x;
                Bs[kq * 4 + 1][m] = vb.y;
                Bs[kq * 4 + 2][m] = vb.z;
                Bs[kq * 4 + 3][m] = vb.w;
            }
            __syncthreads();

            #pragma unroll
            for (int k = 0; k < BK; k++) {
                float a[TM], b[TN];
                #pragma unroll
                for (int i = 0; i < TM; i++) a[i] = As[k][ty * TM + i];
                #pragma unroll
                for (int j = 0; j < TN; j++) b[j] = Bs[k][tx * TN + j];
                #pragma unroll
                for (int i = 0; i < TM; i++)
                    #pragma unroll
                    for (int j = 0; j < TN; j++)
                        acc[i][j] += a[i] * b[j];
            }
        }

        // ---- per-tile argmin epilogue ----
        #pragma unroll
        for (int i = 0; i < TM; i++) {
            float v = e2s[tx * TN] - 2.0f * acc[i][0];
            int   bi = cb0 + tx * TN;
            #pragma unroll
            for (int j = 1; j < TN; j++) {
                float d = e2s[tx * TN + j] - 2.0f * acc[i][j];
                int   c = cb0 + tx * TN + j;
                if (d < v) { v = d; bi = c; }
            }
            // reduce across the 16 tx lanes (contiguous half-warp groups)
            #pragma unroll
            for (int o = 8; o; o >>= 1) {
                float ov = __shfl_xor_sync(0xffffffffu, v, o);
                int   oi = __shfl_xor_sync(0xffffffffu, bi, o);
                if (ov < v || (ov == v && oi < bi)) { v = ov; bi = oi; }
            }
            if (tx == 0) {
                int r = ty * TM + i;
                if (v < bestv[r] || (v == bestv[r] && bi < besti[r])) {
                    bestv[r] = v; besti[r] = bi;
                }
            }
        }
    }

    __syncthreads();

    // ---- gather epilogue: out[row] = codebook[best[row]] ----
    const float4* cb4  = reinterpret_cast<const float4*>(cb);
    float4*       out4 = reinterpret_cast<float4*>(out);
    for (int i = tid; i < BM * (D / 4); i += 256) {
        int r = i >> 7;                // D/4 = 128 float4 per row
        int c = i & 127;
        int idx = besti[r];
        out4[(size_t)(rowBase + r) * (D / 4) + c] =
            cb4[(size_t)idx * (D / 4) + c];
    }
}

// ---------------------------------------------------------------------------
extern "C" void kernel_launch(void* const* d_in, const int* in_sizes, int n_in,
                              void* d_out, int out_size) {
    const float* x  = (const float*)d_in[0];   // [16384, 512]
    const float* cb = (const float*)d_in[1];   // [8192, 512]
    float* out = (float*)d_out;                // [16384, 512]

    e2_kernel<<<K_CB, 128>>>(cb);
    vq_kernel<<<N_ROWS / BM, 256>>>(x, cb, out);
}

// round 4
// speedup vs baseline: 1.8490x; 1.8490x over previous
#include <cuda_runtime.h>
#include <cuda_fp16.h>
#include <cstdint>

// ---------------------------------------------------------------- constants
#define D       512
#define KCAT    2048          // [xh, xh, xl, xl] x [eh, el, eh, el]
#define N_ROWS  16384
#define K_CB    8192
#define BM      128           // rows per block
#define BN      256           // codebook entries per tile
#define KST     32            // k elems per smem stage
#define NSTAGE  (KCAT / KST)  // 64
#define NT      (K_CB / BN)   // 32

// smem layout (bytes): padded row stride = 40 halves = 80 B
#define A_BYTES      (BM * 80)          // 10240
#define B_BYTES      (BN * 80)          // 20480
#define STAGE_BYTES  (A_BYTES + B_BYTES)// 30720
#define OFF_E2S      (2 * STAGE_BYTES)  // 61440, 256 floats
#define OFF_CV       (OFF_E2S + 1024)   // 62464, 4*128 floats
#define OFF_CI       (OFF_CV + 2048)    // 64512, 4*128 ints
#define OFF_BI       (OFF_CI + 2048)    // 66560, 128 ints
#define SMEM_REQ     (OFF_BI + 512)     // 67072

// ---------------------------------------------------------------- scratch
__device__ __half g_xcat[(size_t)N_ROWS * KCAT];
__device__ __half g_ecat[(size_t)K_CB * KCAT];
__device__ float  g_e2[K_CB];

// ---------------------------------------------------------------- prep
// PATTERN=0: [h, h, l, l]  (for x)
// PATTERN=1: [h, l, h, l]  (for codebook)  -> dot(xcat,ecat) = (xh+xl)(eh+el)
template <int PATTERN>
__global__ void __launch_bounds__(256) catsplit_kernel(const float* __restrict__ in,
                                                       __half* __restrict__ out, int n) {
    int i = blockIdx.x * 256 + threadIdx.x;
    if (i >= n) return;
    int row = i >> 9;          // /512
    int c   = i & 511;
    float v = in[i];
    __half h = __float2half_rn(v);
    float hf = __half2float(h);
    __half l = __float2half_rn(v - hf);
    size_t base = (size_t)row * KCAT;
    if (PATTERN == 0) {
        out[base + c]        = h;
        out[base + 512 + c]  = h;
        out[base + 1024 + c] = l;
        out[base + 1536 + c] = l;
    } else {
        out[base + c]        = h;
        out[base + 512 + c]  = l;
        out[base + 1024 + c] = h;
        out[base + 1536 + c] = l;
    }
}

__global__ void __launch_bounds__(128) e2_kernel(const float* __restrict__ cb) {
    int row = blockIdx.x;
    float4 v = reinterpret_cast<const float4*>(cb + (size_t)row * D)[threadIdx.x];
    float s = v.x * v.x + v.y * v.y + v.z * v.z + v.w * v.w;
    #pragma unroll
    for (int o = 16; o; o >>= 1) s += __shfl_xor_sync(0xffffffffu, s, o);
    __shared__ float ws[4];
    if ((threadIdx.x & 31) == 0) ws[threadIdx.x >> 5] = s;
    __syncthreads();
    if (threadIdx.x == 0) g_e2[row] = ws[0] + ws[1] + ws[2] + ws[3];
}

// ---------------------------------------------------------------- mma helper
__device__ __forceinline__ void mma16816(float* c, const uint32_t* a, uint32_t b0, uint32_t b1) {
    asm volatile(
        "mma.sync.aligned.m16n8k16.row.col.f32.f16.f16.f32 "
        "{%0,%1,%2,%3}, {%4,%5,%6,%7}, {%8,%9}, {%0,%1,%2,%3};"
        : "+f"(c[0]), "+f"(c[1]), "+f"(c[2]), "+f"(c[3])
        : "r"(a[0]), "r"(a[1]), "r"(a[2]), "r"(a[3]), "r"(b0), "r"(b1));
}

// ---------------------------------------------------------------- main kernel
__global__ void __launch_bounds__(256, 1) vq_kernel(const __half* __restrict__ xcat,
                                                    const __half* __restrict__ ecat,
                                                    const float* __restrict__ e2,
                                                    const float* __restrict__ cb,
                                                    float* __restrict__ out) {
    extern __shared__ char sm[];
    const int tid  = threadIdx.x;
    const int lane = tid & 31;
    const int wid  = tid >> 5;
    const int wm   = wid >> 2;        // 0..1 (M direction, 64 rows each)
    const int wn   = wid & 3;         // 0..3 (N direction, 64 cols each)
    const int grp  = lane >> 2;       // 0..7
    const int qid  = lane & 3;        // 0..3
    const int rowBase = blockIdx.x * BM;

    float* e2s = (float*)(sm + OFF_E2S);
    float* cv  = (float*)(sm + OFF_CV);
    int*   ci  = (int*)(sm + OFF_CI);

    float runv = 3.4028235e38f;
    int   runi = 0;

    uint4 ra[2], rb[4];

    // -------- prologue: load stage (t=0, s=0) into buffer 0
    {
        #pragma unroll
        for (int it = 0; it < 2; it++) {
            int id = tid + it * 256;
            int r = id >> 2, c = id & 3;
            ra[it] = *(const uint4*)(xcat + (size_t)(rowBase + r) * KCAT + c * 8);
        }
        #pragma unroll
        for (int it = 0; it < 4; it++) {
            int id = tid + it * 256;
            int r = id >> 2, c = id & 3;
            rb[it] = *(const uint4*)(ecat + (size_t)r * KCAT + c * 8);
        }
        char* A = sm;
        char* B = sm + A_BYTES;
        #pragma unroll
        for (int it = 0; it < 2; it++) {
            int id = tid + it * 256;
            *(uint4*)(A + (id >> 2) * 80 + (id & 3) * 16) = ra[it];
        }
        #pragma unroll
        for (int it = 0; it < 4; it++) {
            int id = tid + it * 256;
            *(uint4*)(B + (id >> 2) * 80 + (id & 3) * 16) = rb[it];
        }
        e2s[tid] = e2[tid];
    }
    __syncthreads();

    for (int t = 0; t < NT; t++) {
        float acc[4][8][4];
        #pragma unroll
        for (int mi = 0; mi < 4; mi++)
            #pragma unroll
            for (int ni = 0; ni < 8; ni++)
                #pragma unroll
                for (int j = 0; j < 4; j++) acc[mi][ni][j] = 0.0f;

        for (int s = 0; s < NSTAGE; s++) {
            const int g = t * NSTAGE + s;
            const int buf = g & 1;
            const bool has_next = (g + 1) < NT * NSTAGE;
            const int nt = (s + 1 < NSTAGE) ? t : t + 1;
            const int ns = (s + 1 < NSTAGE) ? s + 1 : 0;

            // ---- issue gmem loads for next stage
            if (has_next) {
                const int d0 = ns * KST;
                const int cb0 = nt * BN;
                #pragma unroll
                for (int it = 0; it < 2; it++) {
                    int id = tid + it * 256;
                    int r = id >> 2, c = id & 3;
                    ra[it] = *(const uint4*)(xcat + (size_t)(rowBase + r) * KCAT + d0 + c * 8);
                }
                #pragma unroll
                for (int it = 0; it < 4; it++) {
                    int id = tid + it * 256;
                    int r = id >> 2, c = id & 3;
                    rb[it] = *(const uint4*)(ecat + (size_t)(cb0 + r) * KCAT + d0 + c * 8);
                }
            }

            // ---- mma on current buffer
            {
                const char* A = sm + buf * STAGE_BYTES;
                const char* B = A + A_BYTES;
                #pragma unroll
                for (int kk = 0; kk < 2; kk++) {
                    uint32_t a[4][4];
                    #pragma unroll
                    for (int mi = 0; mi < 4; mi++) {
                        const char* ab = A + (wm * 64 + mi * 16 + grp) * 80 + kk * 32 + qid * 4;
                        a[mi][0] = *(const uint32_t*)(ab);
                        a[mi][1] = *(const uint32_t*)(ab + 8 * 80);
                        a[mi][2] = *(const uint32_t*)(ab + 16);
                        a[mi][3] = *(const uint32_t*)(ab + 8 * 80 + 16);
                    }
                    #pragma unroll
                    for (int ni = 0; ni < 8; ni++) {
                        const char* bb = B + (wn * 64 + ni * 8 + grp) * 80 + kk * 32 + qid * 4;
                        uint32_t b0 = *(const uint32_t*)(bb);
                        uint32_t b1 = *(const uint32_t*)(bb + 16);
                        #pragma unroll
                        for (int mi = 0; mi < 4; mi++)
                            mma16816(acc[mi][ni], a[mi], b0, b1);
                    }
                }
            }

            // ---- store next stage into other buffer
            if (has_next) {
                char* A = sm + (buf ^ 1) * STAGE_BYTES;
                char* B = A + A_BYTES;
                #pragma unroll
                for (int it = 0; it < 2; it++) {
                    int id = tid + it * 256;
                    *(uint4*)(A + (id >> 2) * 80 + (id & 3) * 16) = ra[it];
                }
                #pragma unroll
                for (int it = 0; it < 4; it++) {
                    int id = tid + it * 256;
                    *(uint4*)(B + (id >> 2) * 80 + (id & 3) * 16) = rb[it];
                }
            }
            __syncthreads();
        }

        // -------- per-tile argmin epilogue
        #pragma unroll
        for (int mi = 0; mi < 4; mi++) {
            #pragma unroll
            for (int h = 0; h < 2; h++) {
                float v = 3.4028235e38f;
                int idx = 0;
                #pragma unroll
                for (int ni = 0; ni < 8; ni++) {
                    #pragma unroll
                    for (int j = 0; j < 2; j++) {
                        int cl = wn * 64 + ni * 8 + qid * 2 + j;
                        float dd = e2s[cl] - 2.0f * acc[mi][ni][h * 2 + j];
                        if (dd < v) { v = dd; idx = cl; }
                    }
                }
                #pragma unroll
                for (int off = 1; off <= 2; off <<= 1) {
                    float ov = __shfl_xor_sync(0xffffffffu, v, off);
                    int   oi = __shfl_xor_sync(0xffffffffu, idx, off);
                    if (ov < v || (ov == v && oi < idx)) { v = ov; idx = oi; }
                }
                if (qid == 0) {
                    int rl = wm * 64 + mi * 16 + grp + h * 8;
                    cv[wn * 128 + rl] = v;
                    ci[wn * 128 + rl] = idx;
                }
            }
        }
        __syncthreads();
        if (tid < 128) {
            #pragma unroll
            for (int w = 0; w < 4; w++) {
                float v = cv[w * 128 + tid];
                int gi = t * BN + ci[w * 128 + tid];
                if (v < runv || (v == runv && gi < runi)) { runv = v; runi = gi; }
            }
        }
        __syncthreads();
        if (t + 1 < NT) e2s[tid] = e2[(t + 1) * BN + tid];
        // next epilogue is 64 barriered stages away; no extra sync needed here
    }

    if (tid < 128) ((int*)(sm + OFF_BI))[tid] = runi;
    __syncthreads();

    // -------- gather: out[row] = cb[best[row]]
    const float4* cb4 = reinterpret_cast<const float4*>(cb);
    float4* out4 = reinterpret_cast<float4*>(out);
    const int* bip = (const int*)(sm + OFF_BI);
    for (int i = tid; i < BM * (D / 4); i += 256) {
        int r = i >> 7, c = i & 127;
        out4[(size_t)(rowBase + r) * (D / 4) + c] = cb4[(size_t)bip[r] * (D / 4) + c];
    }
}

// ---------------------------------------------------------------- launch
extern "C" void kernel_launch(void* const* d_in, const int* in_sizes, int n_in,
                              void* d_out, int out_size) {
    const float* x  = (const float*)d_in[0];   // [16384, 512]
    const float* cb = (const float*)d_in[1];   // [8192, 512]
    float* out = (float*)d_out;

    __half *xcat, *ecat;
    float *e2p;
    cudaGetSymbolAddress((void**)&xcat, g_xcat);
    cudaGetSymbolAddress((void**)&ecat, g_ecat);
    cudaGetSymbolAddress((void**)&e2p, g_e2);

    catsplit_kernel<0><<<(N_ROWS * D + 255) / 256, 256>>>(x, xcat, N_ROWS * D);
    catsplit_kernel<1><<<(K_CB * D + 255) / 256, 256>>>(cb, ecat, K_CB * D);
    e2_kernel<<<K_CB, 128>>>(cb);

    cudaFuncSetAttribute(vq_kernel, cudaFuncAttributeMaxDynamicSharedMemorySize, SMEM_REQ);
    vq_kernel<<<N_ROWS / BM, 256, SMEM_REQ>>>(xcat, ecat, e2p, cb, out);
}

// round 5
// speedup vs baseline: 3.0510x; 1.6501x over previous
#include <cuda_runtime.h>
#include <cuda_fp16.h>
#include <cstdint>

// ---------------------------------------------------------------- constants
#define D       512
#define KCAT    1536          // [xh, xh, xl] x [eh, el, eh]  (ll term dropped)
#define N_ROWS  16384
#define K_CB    8192
#define BM      128           // rows per block
#define BN      256           // codebook entries per tile
#define KST     64            // k elems per smem stage
#define NSTAGE  (KCAT / KST)  // 24
#define NT      (K_CB / BN)   // 32
#define NBUF    4

// smem layout: padded row stride = 72 halves = 144 B (16B aligned, conflict-free frags)
#define RS           144
#define A_BYTES      (BM * RS)            // 18432
#define B_BYTES      (BN * RS)            // 36864
#define STAGE_BYTES  (A_BYTES + B_BYTES)  // 55296
#define OFF_E2S      (NBUF * STAGE_BYTES) // 221184, 256 floats
#define OFF_CV       (OFF_E2S + 1024)
#define OFF_CI       (OFF_CV + 2048)
#define OFF_BI       (OFF_CI + 2048)
#define SMEM_REQ     (OFF_BI + 512)       // 226816 (< 227KB opt-in)

// ---------------------------------------------------------------- scratch
__device__ __half g_xcat[(size_t)N_ROWS * KCAT];
__device__ __half g_ecat[(size_t)K_CB * KCAT];
__device__ float  g_e2[K_CB];

// ---------------------------------------------------------------- prep
// x: [h, h, l]    e: [h, l, h]   -> dot = xh*eh + xh*el + xl*eh  (exact minus ll)
template <int PATTERN>
__global__ void __launch_bounds__(256) catsplit_kernel(const float* __restrict__ in,
                                                       __half* __restrict__ out, int n) {
    int i = blockIdx.x * 256 + threadIdx.x;
    if (i >= n) return;
    int row = i >> 9;          // /512
    int c   = i & 511;
    float v = in[i];
    __half h = __float2half_rn(v);
    float hf = __half2float(h);
    __half l = __float2half_rn(v - hf);
    size_t base = (size_t)row * KCAT;
    if (PATTERN == 0) {        // x side
        out[base + c]        = h;
        out[base + 512 + c]  = h;
        out[base + 1024 + c] = l;
    } else {                   // codebook side
        out[base + c]        = h;
        out[base + 512 + c]  = l;
        out[base + 1024 + c] = h;
    }
}

__global__ void __launch_bounds__(128) e2_kernel(const float* __restrict__ cb) {
    int row = blockIdx.x;
    float4 v = reinterpret_cast<const float4*>(cb + (size_t)row * D)[threadIdx.x];
    float s = v.x * v.x + v.y * v.y + v.z * v.z + v.w * v.w;
    #pragma unroll
    for (int o = 16; o; o >>= 1) s += __shfl_xor_sync(0xffffffffu, s, o);
    __shared__ float ws[4];
    if ((threadIdx.x & 31) == 0) ws[threadIdx.x >> 5] = s;
    __syncthreads();
    if (threadIdx.x == 0) g_e2[row] = ws[0] + ws[1] + ws[2] + ws[3];
}

// ---------------------------------------------------------------- helpers
__device__ __forceinline__ void mma16816(float* c, const uint32_t* a, uint32_t b0, uint32_t b1) {
    asm volatile(
        "mma.sync.aligned.m16n8k16.row.col.f32.f16.f16.f32 "
        "{%0,%1,%2,%3}, {%4,%5,%6,%7}, {%8,%9}, {%0,%1,%2,%3};"
        : "+f"(c[0]), "+f"(c[1]), "+f"(c[2]), "+f"(c[3])
        : "r"(a[0]), "r"(a[1]), "r"(a[2]), "r"(a[3]), "r"(b0), "r"(b1));
}

__device__ __forceinline__ void cp16(void* dst, const void* src) {
    uint32_t d = (uint32_t)__cvta_generic_to_shared(dst);
    asm volatile("cp.async.cg.shared.global [%0], [%1], 16;" :: "r"(d), "l"(src));
}
#define CP_COMMIT() asm volatile("cp.async.commit_group;" ::: "memory")
#define CP_WAIT2()  asm volatile("cp.async.wait_group 2;" ::: "memory")

// ---------------------------------------------------------------- main kernel
__global__ void __launch_bounds__(256, 1) vq_kernel(const __half* __restrict__ xcat,
                                                    const __half* __restrict__ ecat,
                                                    const float* __restrict__ e2,
                                                    const float* __restrict__ cb,
                                                    float* __restrict__ out) {
    extern __shared__ char sm[];
    const int tid  = threadIdx.x;
    const int lane = tid & 31;
    const int wid  = tid >> 5;
    const int wm   = wid >> 2;        // 0..1 (M, 64 rows)
    const int wn   = wid & 3;         // 0..3 (N, 64 cols)
    const int grp  = lane >> 2;       // 0..7
    const int qid  = lane & 3;        // 0..3
    const int rowBase = blockIdx.x * BM;

    float* e2s = (float*)(sm + OFF_E2S);
    float* cv  = (float*)(sm + OFF_CV);
    int*   ci  = (int*)(sm + OFF_CI);

    float runv = 3.4028235e38f;
    int   runi = 0;

    auto issue_stage = [&](int g) {
        const int t = g / NSTAGE;
        const int s = g - t * NSTAGE;
        const int d0 = s * KST;
        const int cb0 = t * BN;
        char* A = sm + (g & (NBUF - 1)) * STAGE_BYTES;
        char* B = A + A_BYTES;
        #pragma unroll
        for (int it = 0; it < 4; it++) {
            int id = tid + it * 256;          // 0..1023
            int r = id >> 3, c = id & 7;
            cp16(A + r * RS + c * 16, xcat + (size_t)(rowBase + r) * KCAT + d0 + c * 8);
        }
        #pragma unroll
        for (int it = 0; it < 8; it++) {
            int id = tid + it * 256;          // 0..2047
            int r = id >> 3, c = id & 7;
            cp16(B + r * RS + c * 16, ecat + (size_t)(cb0 + r) * KCAT + d0 + c * 8);
        }
        CP_COMMIT();
    };

    issue_stage(0); issue_stage(1); issue_stage(2);

    float acc[4][8][4];
    const int S = NT * NSTAGE;                // 768

    for (int g = 0; g < S; g++) {
        const int t = g / NSTAGE;
        const int s = g - t * NSTAGE;

        CP_WAIT2();                           // stage g complete (own thread)
        __syncthreads();                      // visible to all; all done MMA(g-1)

        if (s == 0) {
            e2s[tid] = e2[t * BN + tid];
            #pragma unroll
            for (int mi = 0; mi < 4; mi++)
                #pragma unroll
                for (int ni = 0; ni < 8; ni++)
                    #pragma unroll
                    for (int j = 0; j < 4; j++) acc[mi][ni][j] = 0.0f;
        }

        // ---- MMA on buffer g%4 (KST=64 -> 4 k-steps of 16)
        {
            const char* A = sm + (g & (NBUF - 1)) * STAGE_BYTES;
            const char* B = A + A_BYTES;
            #pragma unroll
            for (int kk = 0; kk < 4; kk++) {
                uint32_t a[4][4];
                #pragma unroll
                for (int mi = 0; mi < 4; mi++) {
                    const char* ab = A + (wm * 64 + mi * 16 + grp) * RS + kk * 32 + qid * 4;
                    a[mi][0] = *(const uint32_t*)(ab);
                    a[mi][1] = *(const uint32_t*)(ab + 8 * RS);
                    a[mi][2] = *(const uint32_t*)(ab + 16);
                    a[mi][3] = *(const uint32_t*)(ab + 8 * RS + 16);
                }
                #pragma unroll
                for (int ni = 0; ni < 8; ni++) {
                    const char* bb = B + (wn * 64 + ni * 8 + grp) * RS + kk * 32 + qid * 4;
                    uint32_t b0 = *(const uint32_t*)(bb);
                    uint32_t b1 = *(const uint32_t*)(bb + 16);
                    #pragma unroll
                    for (int mi = 0; mi < 4; mi++)
                        mma16816(acc[mi][ni], a[mi], b0, b1);
                }
            }
        }

        // ---- per-tile argmin epilogue at tile end
        if (s == NSTAGE - 1) {
            #pragma unroll
            for (int mi = 0; mi < 4; mi++) {
                #pragma unroll
                for (int h = 0; h < 2; h++) {
                    float v = 3.4028235e38f;
                    int idx = 0;
                    #pragma unroll
                    for (int ni = 0; ni < 8; ni++) {
                        #pragma unroll
                        for (int j = 0; j < 2; j++) {
                            int cl = wn * 64 + ni * 8 + qid * 2 + j;
                            float dd = e2s[cl] - 2.0f * acc[mi][ni][h * 2 + j];
                            if (dd < v) { v = dd; idx = cl; }
                        }
                    }
                    #pragma unroll
                    for (int off = 1; off <= 2; off <<= 1) {
                        float ov = __shfl_xor_sync(0xffffffffu, v, off);
                        int   oi = __shfl_xor_sync(0xffffffffu, idx, off);
                        if (ov < v || (ov == v && oi < idx)) { v = ov; idx = oi; }
                    }
                    if (qid == 0) {
                        int rl = wm * 64 + mi * 16 + grp + h * 8;
                        cv[wn * 128 + rl] = v;
                        ci[wn * 128 + rl] = idx;
                    }
                }
            }
            __syncthreads();
            if (tid < 128) {
                #pragma unroll
                for (int w = 0; w < 4; w++) {
                    float v = cv[w * 128 + tid];
                    int gi = t * BN + ci[w * 128 + tid];
                    if (v < runv || (v == runv && gi < runi)) { runv = v; runi = gi; }
                }
            }
            // no sync needed: next read of cv/ci is >= 1 full tile (24 barriers) away
        }

        if (g + NBUF - 1 < S) issue_stage(g + NBUF - 1);
    }

    if (tid < 128) ((int*)(sm + OFF_BI))[tid] = runi;
    __syncthreads();

    // -------- gather: out[row] = cb[best[row]]
    const float4* cb4 = reinterpret_cast<const float4*>(cb);
    float4* out4 = reinterpret_cast<float4*>(out);
    const int* bip = (const int*)(sm + OFF_BI);
    for (int i = tid; i < BM * (D / 4); i += 256) {
        int r = i >> 7, c = i & 127;
        out4[(size_t)(rowBase + r) * (D / 4) + c] = cb4[(size_t)bip[r] * (D / 4) + c];
    }
}

// ---------------------------------------------------------------- launch
extern "C" void kernel_launch(void* const* d_in, const int* in_sizes, int n_in,
                              void* d_out, int out_size) {
    const float* x  = (const float*)d_in[0];   // [16384, 512]
    const float* cb = (const float*)d_in[1];   // [8192, 512]
    float* out = (float*)d_out;

    __half *xcat, *ecat;
    float *e2p;
    cudaGetSymbolAddress((void**)&xcat, g_xcat);
    cudaGetSymbolAddress((void**)&ecat, g_ecat);
    cudaGetSymbolAddress((void**)&e2p, g_e2);

    catsplit_kernel<0><<<(N_ROWS * D + 255) / 256, 256>>>(x, xcat, N_ROWS * D);
    catsplit_kernel<1><<<(K_CB * D + 255) / 256, 256>>>(cb, ecat, K_CB * D);
    e2_kernel<<<K_CB, 128>>>(cb);

    cudaFuncSetAttribute(vq_kernel, cudaFuncAttributeMaxDynamicSharedMemorySize, SMEM_REQ);
    vq_kernel<<<N_ROWS / BM, 256, SMEM_REQ>>>(xcat, ecat, e2p, cb, out);
}

// round 6
// speedup vs baseline: 3.3173x; 1.0873x over previous
#include <cuda_runtime.h>
#include <cuda_fp16.h>
#include <cstdint>

// ---------------------------------------------------------------- constants
#define D       512
#define KCAT    1536          // [xh, xh, xl] x [eh, el, eh]  (ll term dropped)
#define N_ROWS  16384
#define K_CB    8192
#define BM      128
#define BN      256
#define KST     64            // k elems per smem stage
#define NSTAGE  (KCAT / KST)  // 24
#define NT      (K_CB / BN)   // 32
#define NBUF    4
#define NTHR    512

// padded row stride = 144 B (ldmatrix conflict-free: 36 words/row)
#define RS           144
#define A_BYTES      (BM * RS)            // 18432
#define B_BYTES      (BN * RS)            // 36864
#define STAGE_BYTES  (A_BYTES + B_BYTES)  // 55296
#define OFF_E2S      (NBUF * STAGE_BYTES) // 221184
#define OFF_CV       (OFF_E2S + 1024)
#define OFF_CI       (OFF_CV + 2048)
#define OFF_BI       (OFF_CI + 2048)
#define SMEM_REQ     (OFF_BI + 512)       // 226816

// ---------------------------------------------------------------- scratch
__device__ __half g_xcat[(size_t)N_ROWS * KCAT];
__device__ __half g_ecat[(size_t)K_CB * KCAT];
__device__ float  g_e2[K_CB];

// ---------------------------------------------------------------- prep
template <int PATTERN>
__global__ void __launch_bounds__(256) catsplit_kernel(const float* __restrict__ in,
                                                       __half* __restrict__ out, int n) {
    int i = blockIdx.x * 256 + threadIdx.x;
    if (i >= n) return;
    int row = i >> 9;
    int c   = i & 511;
    float v = in[i];
    __half h = __float2half_rn(v);
    float hf = __half2float(h);
    __half l = __float2half_rn(v - hf);
    size_t base = (size_t)row * KCAT;
    if (PATTERN == 0) {        // x side: [h, h, l]
        out[base + c]        = h;
        out[base + 512 + c]  = h;
        out[base + 1024 + c] = l;
    } else {                   // codebook side: [h, l, h]
        out[base + c]        = h;
        out[base + 512 + c]  = l;
        out[base + 1024 + c] = h;
    }
}

__global__ void __launch_bounds__(128) e2_kernel(const float* __restrict__ cb) {
    int row = blockIdx.x;
    float4 v = reinterpret_cast<const float4*>(cb + (size_t)row * D)[threadIdx.x];
    float s = v.x * v.x + v.y * v.y + v.z * v.z + v.w * v.w;
    #pragma unroll
    for (int o = 16; o; o >>= 1) s += __shfl_xor_sync(0xffffffffu, s, o);
    __shared__ float ws[4];
    if ((threadIdx.x & 31) == 0) ws[threadIdx.x >> 5] = s;
    __syncthreads();
    if (threadIdx.x == 0) g_e2[row] = ws[0] + ws[1] + ws[2] + ws[3];
}

// ---------------------------------------------------------------- helpers
__device__ __forceinline__ void mma16816(float* c, const uint32_t* a, uint32_t b0, uint32_t b1) {
    asm volatile(
        "mma.sync.aligned.m16n8k16.row.col.f32.f16.f16.f32 "
        "{%0,%1,%2,%3}, {%4,%5,%6,%7}, {%8,%9}, {%0,%1,%2,%3};"
        : "+f"(c[0]), "+f"(c[1]), "+f"(c[2]), "+f"(c[3])
        : "r"(a[0]), "r"(a[1]), "r"(a[2]), "r"(a[3]), "r"(b0), "r"(b1));
}

__device__ __forceinline__ void ldmat4(uint32_t& r0, uint32_t& r1, uint32_t& r2, uint32_t& r3,
                                       uint32_t addr) {
    asm volatile("ldmatrix.sync.aligned.m8n8.x4.shared.b16 {%0,%1,%2,%3}, [%4];"
                 : "=r"(r0), "=r"(r1), "=r"(r2), "=r"(r3) : "r"(addr));
}

__device__ __forceinline__ void cp16(uint32_t dst, const void* src) {
    asm volatile("cp.async.cg.shared.global [%0], [%1], 16;" :: "r"(dst), "l"(src));
}
#define CP_COMMIT() asm volatile("cp.async.commit_group;" ::: "memory")
#define CP_WAIT2()  asm volatile("cp.async.wait_group 2;" ::: "memory")

__device__ __forceinline__ uint32_t smem_u32(const void* p) {
    return (uint32_t)__cvta_generic_to_shared(p);
}

// ---------------------------------------------------------------- main kernel
__global__ void __launch_bounds__(NTHR, 1) vq_kernel(const __half* __restrict__ xcat,
                                                     const __half* __restrict__ ecat,
                                                     const float* __restrict__ e2,
                                                     const float* __restrict__ cb,
                                                     float* __restrict__ out) {
    extern __shared__ char sm[];
    const uint32_t smb = smem_u32(sm);
    const int tid  = threadIdx.x;
    const int lane = tid & 31;
    const int wid  = tid >> 5;
    const int wm   = wid >> 2;        // 0..3 (M, 32 rows each)
    const int wn   = wid & 3;         // 0..3 (N, 64 cols each)
    const int grp  = lane >> 2;       // 0..7
    const int qid  = lane & 3;        // 0..3
    const int rowBase = blockIdx.x * BM;

    float* e2s = (float*)(sm + OFF_E2S);
    float* cv  = (float*)(sm + OFF_CV);
    int*   ci  = (int*)(sm + OFF_CI);

    float runv = 3.4028235e38f;
    int   runi = 0;

    // per-lane ldmatrix address components (hoisted)
    const uint32_t aRow = (uint32_t)(wm * 32 + (lane & 15));          // + mi*16
    const uint32_t aCol = (uint32_t)((lane >> 4) * 16);
    const uint32_t bRow = (uint32_t)(wn * 64 + (lane >> 4) * 8 + (lane & 7)); // + p*16
    const uint32_t bCol = (uint32_t)(((lane >> 3) & 1) * 16);

    auto issue_stage = [&](int g) {
        const int t = g / NSTAGE;
        const int s = g - t * NSTAGE;
        const int d0 = s * KST;
        const int cb0 = t * BN;
        uint32_t A = smb + (g & (NBUF - 1)) * STAGE_BYTES;
        uint32_t B = A + A_BYTES;
        #pragma unroll
        for (int it = 0; it < 2; it++) {
            int id = tid + it * NTHR;         // 0..1023
            int r = id >> 3, c = id & 7;
            cp16(A + r * RS + c * 16, xcat + (size_t)(rowBase + r) * KCAT + d0 + c * 8);
        }
        #pragma unroll
        for (int it = 0; it < 4; it++) {
            int id = tid + it * NTHR;         // 0..2047
            int r = id >> 3, c = id & 7;
            cp16(B + r * RS + c * 16, ecat + (size_t)(cb0 + r) * KCAT + d0 + c * 8);
        }
        CP_COMMIT();
    };

    issue_stage(0); issue_stage(1); issue_stage(2);

    float acc[2][8][4];
    const int S = NT * NSTAGE;                // 768

    for (int g = 0; g < S; g++) {
        const int t = g / NSTAGE;
        const int s = g - t * NSTAGE;

        CP_WAIT2();
        __syncthreads();

        if (s == 0) {
            if (tid < BN) e2s[tid] = e2[t * BN + tid];
            #pragma unroll
            for (int mi = 0; mi < 2; mi++)
                #pragma unroll
                for (int ni = 0; ni < 8; ni++)
                    #pragma unroll
                    for (int j = 0; j < 4; j++) acc[mi][ni][j] = 0.0f;
        }

        // ---- MMA on buffer g%4 (KST=64 -> 4 k-steps of 16)
        {
            uint32_t A = smb + (g & (NBUF - 1)) * STAGE_BYTES;
            uint32_t B = A + A_BYTES;
            #pragma unroll
            for (int kk = 0; kk < 4; kk++) {
                uint32_t a[2][4];
                #pragma unroll
                for (int mi = 0; mi < 2; mi++)
                    ldmat4(a[mi][0], a[mi][1], a[mi][2], a[mi][3],
                           A + (aRow + mi * 16) * RS + kk * 32 + aCol);
                #pragma unroll
                for (int p = 0; p < 4; p++) {
                    uint32_t b0, b1, b2, b3;
                    ldmat4(b0, b1, b2, b3, B + (bRow + p * 16) * RS + kk * 32 + bCol);
                    #pragma unroll
                    for (int mi = 0; mi < 2; mi++) {
                        mma16816(acc[mi][2 * p],     a[mi], b0, b1);
                        mma16816(acc[mi][2 * p + 1], a[mi], b2, b3);
                    }
                }
            }
        }

        // ---- per-tile argmin epilogue at tile end
        if (s == NSTAGE - 1) {
            #pragma unroll
            for (int mi = 0; mi < 2; mi++) {
                #pragma unroll
                for (int h = 0; h < 2; h++) {
                    float v = 3.4028235e38f;
                    int idx = 0;
                    #pragma unroll
                    for (int ni = 0; ni < 8; ni++) {
                        #pragma unroll
                        for (int j = 0; j < 2; j++) {
                            int cl = wn * 64 + ni * 8 + qid * 2 + j;
                            float dd = e2s[cl] - 2.0f * acc[mi][ni][h * 2 + j];
                            if (dd < v) { v = dd; idx = cl; }
                        }
                    }
                    #pragma unroll
                    for (int off = 1; off <= 2; off <<= 1) {
                        float ov = __shfl_xor_sync(0xffffffffu, v, off);
                        int   oi = __shfl_xor_sync(0xffffffffu, idx, off);
                        if (ov < v || (ov == v && oi < idx)) { v = ov; idx = oi; }
                    }
                    if (qid == 0) {
                        int rl = wm * 32 + mi * 16 + grp + h * 8;
                        cv[wn * 128 + rl] = v;
                        ci[wn * 128 + rl] = idx;
                    }
                }
            }
            __syncthreads();
            if (tid < BM) {
                #pragma unroll
                for (int w = 0; w < 4; w++) {
                    float v = cv[w * 128 + tid];
                    int gi = t * BN + ci[w * 128 + tid];
                    if (v < runv || (v == runv && gi < runi)) { runv = v; runi = gi; }
                }
            }
            // next write of cv/ci is a full tile (24 barriers) away
        }

        if (g + NBUF - 1 < S) issue_stage(g + NBUF - 1);
    }

    if (tid < BM) ((int*)(sm + OFF_BI))[tid] = runi;
    __syncthreads();

    // -------- gather: out[row] = cb[best[row]]
    const float4* cb4 = reinterpret_cast<const float4*>(cb);
    float4* out4 = reinterpret_cast<float4*>(out);
    const int* bip = (const int*)(sm + OFF_BI);
    for (int i = tid; i < BM * (D / 4); i += NTHR) {
        int r = i >> 7, c = i & 127;
        out4[(size_t)(rowBase + r) * (D / 4) + c] = cb4[(size_t)bip[r] * (D / 4) + c];
    }
}

// ---------------------------------------------------------------- launch
extern "C" void kernel_launch(void* const* d_in, const int* in_sizes, int n_in,
                              void* d_out, int out_size) {
    const float* x  = (const float*)d_in[0];
    const float* cb = (const float*)d_in[1];
    float* out = (float*)d_out;

    __half *xcat, *ecat;
    float *e2p;
    cudaGetSymbolAddress((void**)&xcat, g_xcat);
    cudaGetSymbolAddress((void**)&ecat, g_ecat);
    cudaGetSymbolAddress((void**)&e2p, g_e2);

    catsplit_kernel<0><<<(N_ROWS * D + 255) / 256, 256>>>(x, xcat, N_ROWS * D);
    catsplit_kernel<1><<<(K_CB * D + 255) / 256, 256>>>(cb, ecat, K_CB * D);
    e2_kernel<<<K_CB, 128>>>(cb);

    cudaFuncSetAttribute(vq_kernel, cudaFuncAttributeMaxDynamicSharedMemorySize, SMEM_REQ);
    vq_kernel<<<N_ROWS / BM, NTHR, SMEM_REQ>>>(xcat, ecat, e2p, cb, out);
}